// round 2
// baseline (speedup 1.0000x reference)
#include <cuda_runtime.h>

#define THREADS 256
#define WARPS 8          // warps per block
#define PTS 8            // points per block (one per warp for row-parallel stages)
#define ROWPAD 260       // 256 rows + pad (keeps row bases 16B-aligned)

typedef unsigned long long u64;

struct __align__(16) Smem {
  float w2[32][64];     // 8 KB
  float w3[64][64];     // 16 KB
  float ow[64][128];    // 32 KB
  float w1[6][32];
  float b1[32], g1[32], be1[32];
  float b2[64], g2[64], be2[64];
  float b3[64];
  float ob[128], lg[128], lb[128];
  float xT[32][ROWPAD];  // layer-1 output, transposed: [feat][pt*32+lane]
  float hT[64][ROWPAD];  // layer-2 output, transposed
  float ctr[PTS][64];    // per-point contracted (max over K)
};

__device__ __forceinline__ u64 pack2(float x, float y) {
  u64 r; asm("mov.b64 %0, {%1, %2};" : "=l"(r) : "f"(x), "f"(y)); return r;
}
__device__ __forceinline__ void unpack2(u64 v, float &x, float &y) {
  asm("mov.b64 {%0, %1}, %2;" : "=f"(x), "=f"(y) : "l"(v));
}
// Packed 2xfp32 FMA (Blackwell sm_100+).
__device__ __forceinline__ u64 ffma2(u64 a, u64 b, u64 c) {
  u64 d; asm("fma.rn.f32x2 %0, %1, %2, %3;" : "=l"(d) : "l"(a), "l"(b), "l"(c));
  return d;
}

__device__ __forceinline__ float wsum(float v) {
  #pragma unroll
  for (int o = 16; o > 0; o >>= 1) v += __shfl_xor_sync(0xffffffffu, v, o);
  return v;
}

__device__ __forceinline__ void cpy(float* d, const float* s, int n) {
  for (int i = threadIdx.x; i < n; i += THREADS) d[i] = s[i];
}

extern "C" __global__ void __launch_bounds__(THREADS)
so3conv_kernel(const float* __restrict__ pts, const float* __restrict__ nbr,
               const float* __restrict__ w1, const float* __restrict__ b1,
               const float* __restrict__ g1, const float* __restrict__ be1,
               const float* __restrict__ w2, const float* __restrict__ b2,
               const float* __restrict__ g2, const float* __restrict__ be2,
               const float* __restrict__ w3, const float* __restrict__ b3,
               const float* __restrict__ ow, const float* __restrict__ ob,
               const float* __restrict__ lg, const float* __restrict__ lb,
               float* __restrict__ out)
{
  extern __shared__ float smem_raw[];
  Smem* s = reinterpret_cast<Smem*>(smem_raw);
  cpy(&s->w2[0][0], w2, 32 * 64);
  cpy(&s->w3[0][0], w3, 64 * 64);
  cpy(&s->ow[0][0], ow, 64 * 128);
  cpy(&s->w1[0][0], w1, 6 * 32);
  cpy(s->b1, b1, 32); cpy(s->g1, g1, 32); cpy(s->be1, be1, 32);
  cpy(s->b2, b2, 64); cpy(s->g2, g2, 64); cpy(s->be2, be2, 64);
  cpy(s->b3, b3, 64);
  cpy(s->ob, ob, 128); cpy(s->lg, lg, 128); cpy(s->lb, lb, 128);
  __syncthreads();

  const int tid  = threadIdx.x;
  const int warp = tid >> 5;
  const int lane = tid & 31;
  const int point = blockIdx.x * PTS + warp;   // warp <-> point for row stages

  // ================= rifeat (warp = point, lane = neighbor) =================
  const float px = pts[point * 3 + 0];
  const float py = pts[point * 3 + 1];
  const float pz = pts[point * 3 + 2];
  const float* nb = nbr + (size_t)point * 96 + lane * 3;
  const float nx = nb[0], ny = nb[1], nz = nb[2];

  const float mx = wsum(nx) * 0.03125f;
  const float my = wsum(ny) * 0.03125f;
  const float mz = wsum(nz) * 0.03125f;

  const float l1x = mx - nx, l1y = my - ny, l1z = mz - nz;
  const float l2x = nx - px, l2y = ny - py, l2z = nz - pz;
  const float l3x = px - mx, l3y = py - my, l3z = pz - mz;
  const float n1 = sqrtf(l1x * l1x + l1y * l1y + l1z * l1z);
  const float n2 = sqrtf(l2x * l2x + l2y * l2y + l2z * l2z);
  const float n3 = sqrtf(l3x * l3x + l3y * l3y + l3z * l3z);
  const float d12 = l1x * l2x + l1y * l2y + l1z * l2z;
  const float d23 = l2x * l3x + l2y * l3y + l2z * l3z;
  const float d31 = l3x * l1x + l3y * l1y + l3z * l1z;
  float f[6];
  f[0] = n1; f[1] = n2; f[2] = n3;
  f[3] = d12 / (n1 * n2 + 1e-7f);
  f[4] = d23 / (n2 * n3 + 1e-7f);
  f[5] = d31 / (n3 * n1 + 1e-7f);

  // ========== layer 1: [6]@[6,32] + b1, LN(32) lane-local, relu ==========
  {
    float x[32];
    #pragma unroll
    for (int j = 0; j < 32; ++j) x[j] = s->b1[j];
    #pragma unroll
    for (int i = 0; i < 6; ++i) {
      const float a = f[i];
      #pragma unroll
      for (int j = 0; j < 32; ++j) x[j] += a * s->w1[i][j];
    }
    float sm = 0.f;
    #pragma unroll
    for (int j = 0; j < 32; ++j) sm += x[j];
    const float mu = sm * (1.f / 32.f);
    float vs = 0.f;
    #pragma unroll
    for (int j = 0; j < 32; ++j) { const float d = x[j] - mu; vs += d * d; }
    const float inv = rsqrtf(vs * (1.f / 32.f) + 1e-5f);
    #pragma unroll
    for (int j = 0; j < 32; ++j)
      s->xT[j][tid] = fmaxf(0.f, (x[j] - mu) * inv * s->g1[j] + s->be1[j]);
  }
  __syncthreads();

  // ===== layer 2 (block-cooperative): warp owns cols [8w,8w+8) for ALL 8 pts
  {
    const int c0 = warp * 8;
    u64 acc[PTS][4];
    u64 bp[4];
    #pragma unroll
    for (int c = 0; c < 4; ++c) bp[c] = *reinterpret_cast<const u64*>(&s->b2[c0 + 2*c]);
    #pragma unroll
    for (int p = 0; p < PTS; ++p)
      #pragma unroll
      for (int c = 0; c < 4; ++c) acc[p][c] = bp[c];

    #pragma unroll
    for (int i = 0; i < 32; ++i) {
      const ulonglong2 wA = *reinterpret_cast<const ulonglong2*>(&s->w2[i][c0]);
      const ulonglong2 wB = *reinterpret_cast<const ulonglong2*>(&s->w2[i][c0 + 4]);
      const float* xr = &s->xT[i][lane];
      #pragma unroll
      for (int p = 0; p < PTS; ++p) {
        const float a = xr[p * 32];
        const u64 aa = pack2(a, a);
        acc[p][0] = ffma2(wA.x, aa, acc[p][0]);
        acc[p][1] = ffma2(wA.y, aa, acc[p][1]);
        acc[p][2] = ffma2(wB.x, aa, acc[p][2]);
        acc[p][3] = ffma2(wB.y, aa, acc[p][3]);
      }
    }
    // write raw h (transposed)
    #pragma unroll
    for (int p = 0; p < PTS; ++p) {
      #pragma unroll
      for (int c = 0; c < 4; ++c) {
        float a, b; unpack2(acc[p][c], a, b);
        s->hT[c0 + 2*c][p * 32 + lane]     = a;
        s->hT[c0 + 2*c + 1][p * 32 + lane] = b;
      }
    }
  }
  __syncthreads();

  // ========== LN(64) + relu, thread = row, in place on hT ==========
  {
    float v[64];
    float sm = 0.f;
    #pragma unroll
    for (int i = 0; i < 64; ++i) { v[i] = s->hT[i][tid]; sm += v[i]; }
    const float mu = sm * (1.f / 64.f);
    float vs = 0.f;
    #pragma unroll
    for (int i = 0; i < 64; ++i) { const float d = v[i] - mu; vs += d * d; }
    const float inv = rsqrtf(vs * (1.f / 64.f) + 1e-5f);
    #pragma unroll
    for (int i = 0; i < 64; ++i)
      s->hT[i][tid] = fmaxf(0.f, (v[i] - mu) * inv * s->g2[i] + s->be2[i]);
  }
  __syncthreads();

  // ===== layer 3 (block-cooperative) + max over K (butterfly) =====
  {
    const int c0 = warp * 8;
    u64 acc[PTS][4];
    u64 bp[4];
    #pragma unroll
    for (int c = 0; c < 4; ++c) bp[c] = *reinterpret_cast<const u64*>(&s->b3[c0 + 2*c]);
    #pragma unroll
    for (int p = 0; p < PTS; ++p)
      #pragma unroll
      for (int c = 0; c < 4; ++c) acc[p][c] = bp[c];

    #pragma unroll
    for (int i = 0; i < 64; ++i) {
      const ulonglong2 wA = *reinterpret_cast<const ulonglong2*>(&s->w3[i][c0]);
      const ulonglong2 wB = *reinterpret_cast<const ulonglong2*>(&s->w3[i][c0 + 4]);
      const float* hr = &s->hT[i][lane];
      #pragma unroll
      for (int p = 0; p < PTS; ++p) {
        const float a = hr[p * 32];
        const u64 aa = pack2(a, a);
        acc[p][0] = ffma2(wA.x, aa, acc[p][0]);
        acc[p][1] = ffma2(wA.y, aa, acc[p][1]);
        acc[p][2] = ffma2(wB.x, aa, acc[p][2]);
        acc[p][3] = ffma2(wB.y, aa, acc[p][3]);
      }
    }
    // max over rows (lanes) per point, then store to ctr
    #pragma unroll
    for (int p = 0; p < PTS; ++p) {
      float m[8];
      #pragma unroll
      for (int c = 0; c < 4; ++c) unpack2(acc[p][c], m[2*c], m[2*c + 1]);
      #pragma unroll
      for (int off = 16; off > 0; off >>= 1) {
        #pragma unroll
        for (int c = 0; c < 8; ++c)
          m[c] = fmaxf(m[c], __shfl_xor_sync(0xffffffffu, m[c], off));
      }
      #pragma unroll
      for (int c = 0; c < 8; ++c)
        if (lane == c) s->ctr[p][c0 + c] = m[c];
    }
  }
  __syncthreads();

  // ========== layer 4: warp = point; lane = 4 output cols; LN(128) ==========
  {
    const float* ctr = s->ctr[warp];
    float4 a = *reinterpret_cast<const float4*>(&s->ob[4 * lane]);
    #pragma unroll
    for (int i = 0; i < 64; ++i) {
      const float c = ctr[i];
      const float4 w = *reinterpret_cast<const float4*>(&s->ow[i][4 * lane]);
      a.x += c * w.x; a.y += c * w.y; a.z += c * w.z; a.w += c * w.w;
    }
    const float sm = wsum(a.x + a.y + a.z + a.w);
    const float mu = sm * (1.f / 128.f);
    const float dx = a.x - mu, dy = a.y - mu, dz = a.z - mu, dw = a.w - mu;
    const float vs = wsum(dx * dx + dy * dy + dz * dz + dw * dw);
    const float inv = rsqrtf(vs * (1.f / 128.f) + 1e-5f);
    const float4 g  = *reinterpret_cast<const float4*>(&s->lg[4 * lane]);
    const float4 bb = *reinterpret_cast<const float4*>(&s->lb[4 * lane]);
    float4 o;
    o.x = dx * inv * g.x + bb.x;
    o.y = dy * inv * g.y + bb.y;
    o.z = dz * inv * g.z + bb.z;
    o.w = dw * inv * g.w + bb.w;
    *reinterpret_cast<float4*>(&out[(size_t)point * 128 + 4 * lane]) = o;
  }
}

extern "C" void kernel_launch(void* const* d_in, const int* in_sizes, int n_in,
                              void* d_out, int out_size) {
  const float* pts = (const float*)d_in[0];
  const float* nbr = (const float*)d_in[1];
  const float* w1  = (const float*)d_in[2];
  const float* b1  = (const float*)d_in[3];
  const float* g1  = (const float*)d_in[4];
  const float* be1 = (const float*)d_in[5];
  const float* w2  = (const float*)d_in[6];
  const float* b2  = (const float*)d_in[7];
  const float* g2  = (const float*)d_in[8];
  const float* be2 = (const float*)d_in[9];
  const float* w3  = (const float*)d_in[10];
  const float* b3  = (const float*)d_in[11];
  const float* ow  = (const float*)d_in[12];
  const float* ob  = (const float*)d_in[13];
  const float* lg  = (const float*)d_in[14];
  const float* lb  = (const float*)d_in[15];

  const int P = in_sizes[1] / 96;          // B*N points
  const int grid = P / PTS;                // 4096

  cudaFuncSetAttribute(so3conv_kernel,
                       cudaFuncAttributeMaxDynamicSharedMemorySize,
                       (int)sizeof(Smem));
  so3conv_kernel<<<grid, THREADS, sizeof(Smem)>>>(
      pts, nbr, w1, b1, g1, be1, w2, b2, g2, be2, w3, b3,
      ow, ob, lg, lb, (float*)d_out);
}

// round 4
// speedup vs baseline: 1.3391x; 1.3391x over previous
#include <cuda_runtime.h>

#define THREADS 256
#define WARPS 8
#define PTS 8            // points per block
#define ROWS 256         // PTS * 32 neighbor rows

typedef unsigned long long u64;

// ---- shared memory layout (floats), phase-unioned ----
// R region (16384 floats = 64KB):
//   phase A/B:  w2 = R[0 .. 2048),  xT = R[2048 .. 2048+32*256)
//   phase C:    hT = R[0 .. 64*256)
// then: w3 (4096), w1 (192), small vectors, ctr.
#define OFF_R      0
#define OFF_W2     0
#define OFF_XT     2048
#define OFF_HT     0
#define OFF_W3     16384
#define OFF_W1     (OFF_W3 + 4096)
#define OFF_B1     (OFF_W1 + 192)
#define OFF_G1     (OFF_B1 + 32)
#define OFF_BE1    (OFF_G1 + 32)
#define OFF_B2     (OFF_BE1 + 32)
#define OFF_G2     (OFF_B2 + 64)
#define OFF_BE2    (OFF_G2 + 64)
#define OFF_B3     (OFF_BE2 + 64)
#define OFF_OB     (OFF_B3 + 64)
#define OFF_LG     (OFF_OB + 128)
#define OFF_LB     (OFF_LG + 128)
#define OFF_CTR    (OFF_LB + 128)
#define SMEM_FLOATS (OFF_CTR + PTS * 64)

__device__ __forceinline__ u64 pack2(float x, float y) {
  u64 r; asm("mov.b64 %0, {%1, %2};" : "=l"(r) : "f"(x), "f"(y)); return r;
}
__device__ __forceinline__ void unpack2(u64 v, float &x, float &y) {
  asm("mov.b64 {%0, %1}, %2;" : "=f"(x), "=f"(y) : "l"(v));
}
// Packed 2xfp32 FMA (sm_100+).
__device__ __forceinline__ u64 ffma2(u64 a, u64 b, u64 c) {
  u64 d; asm("fma.rn.f32x2 %0, %1, %2, %3;" : "=l"(d) : "l"(a), "l"(b), "l"(c));
  return d;
}

__device__ __forceinline__ float wsum(float v) {
  #pragma unroll
  for (int o = 16; o > 0; o >>= 1) v += __shfl_xor_sync(0xffffffffu, v, o);
  return v;
}

__device__ __forceinline__ void cpy(float* d, const float* s, int n) {
  for (int i = threadIdx.x; i < n; i += THREADS) d[i] = s[i];
}

extern "C" __global__ void __launch_bounds__(THREADS, 2)
so3conv_kernel(const float* __restrict__ pts, const float* __restrict__ nbr,
               const float* __restrict__ w1, const float* __restrict__ b1,
               const float* __restrict__ g1, const float* __restrict__ be1,
               const float* __restrict__ w2, const float* __restrict__ b2,
               const float* __restrict__ g2, const float* __restrict__ be2,
               const float* __restrict__ w3, const float* __restrict__ b3,
               const float* __restrict__ ow, const float* __restrict__ ob,
               const float* __restrict__ lg, const float* __restrict__ lb,
               float* __restrict__ out)
{
  extern __shared__ float s[];
  cpy(s + OFF_W2, w2, 32 * 64);
  cpy(s + OFF_W3, w3, 64 * 64);
  cpy(s + OFF_W1, w1, 6 * 32);
  cpy(s + OFF_B1, b1, 32); cpy(s + OFF_G1, g1, 32); cpy(s + OFF_BE1, be1, 32);
  cpy(s + OFF_B2, b2, 64); cpy(s + OFF_G2, g2, 64); cpy(s + OFF_BE2, be2, 64);
  cpy(s + OFF_B3, b3, 64);
  cpy(s + OFF_OB, ob, 128); cpy(s + OFF_LG, lg, 128); cpy(s + OFF_LB, lb, 128);
  __syncthreads();

  const int tid  = threadIdx.x;
  const int warp = tid >> 5;
  const int lane = tid & 31;
  const int point = blockIdx.x * PTS + warp;

  // ================= rifeat (warp = point, lane = neighbor) =================
  const float px = pts[point * 3 + 0];
  const float py = pts[point * 3 + 1];
  const float pz = pts[point * 3 + 2];
  const float* nb = nbr + (size_t)point * 96 + lane * 3;
  const float nx = nb[0], ny = nb[1], nz = nb[2];

  const float mx = wsum(nx) * 0.03125f;
  const float my = wsum(ny) * 0.03125f;
  const float mz = wsum(nz) * 0.03125f;

  const float l1x = mx - nx, l1y = my - ny, l1z = mz - nz;
  const float l2x = nx - px, l2y = ny - py, l2z = nz - pz;
  const float l3x = px - mx, l3y = py - my, l3z = pz - mz;
  const float n1 = sqrtf(l1x * l1x + l1y * l1y + l1z * l1z);
  const float n2 = sqrtf(l2x * l2x + l2y * l2y + l2z * l2z);
  const float n3 = sqrtf(l3x * l3x + l3y * l3y + l3z * l3z);
  const float d12 = l1x * l2x + l1y * l2y + l1z * l2z;
  const float d23 = l2x * l3x + l2y * l3y + l2z * l3z;
  const float d31 = l3x * l1x + l3y * l1y + l3z * l1z;
  float f[6];
  f[0] = n1; f[1] = n2; f[2] = n3;
  f[3] = d12 / (n1 * n2 + 1e-7f);
  f[4] = d23 / (n2 * n3 + 1e-7f);
  f[5] = d31 / (n3 * n1 + 1e-7f);

  // ========== layer 1: [6]@[6,32] + b1, LN(32) lane-local, relu ==========
  {
    float x[32];
    #pragma unroll
    for (int j = 0; j < 32; ++j) x[j] = s[OFF_B1 + j];
    #pragma unroll
    for (int i = 0; i < 6; ++i) {
      const float a = f[i];
      #pragma unroll
      for (int j = 0; j < 32; ++j) x[j] += a * s[OFF_W1 + i * 32 + j];
    }
    float sm = 0.f;
    #pragma unroll
    for (int j = 0; j < 32; ++j) sm += x[j];
    const float mu = sm * (1.f / 32.f);
    float vs = 0.f;
    #pragma unroll
    for (int j = 0; j < 32; ++j) { const float d = x[j] - mu; vs += d * d; }
    const float inv = rsqrtf(vs * (1.f / 32.f) + 1e-5f);
    #pragma unroll
    for (int j = 0; j < 32; ++j)
      s[OFF_XT + j * ROWS + tid] =
          fmaxf(0.f, (x[j] - mu) * inv * s[OFF_G1 + j] + s[OFF_BE1 + j]);
  }
  __syncthreads();

  // ===== layer 2 (block-coop): warp owns cols [8w,8w+8) for all 8 points
  u64 acc[PTS][4];
  {
    const int c0 = warp * 8;
    u64 bp[4];
    #pragma unroll
    for (int c = 0; c < 4; ++c)
      bp[c] = *reinterpret_cast<const u64*>(&s[OFF_B2 + c0 + 2 * c]);
    #pragma unroll
    for (int p = 0; p < PTS; ++p)
      #pragma unroll
      for (int c = 0; c < 4; ++c) acc[p][c] = bp[c];

    #pragma unroll
    for (int i = 0; i < 32; ++i) {
      const ulonglong2 wA = *reinterpret_cast<const ulonglong2*>(&s[OFF_W2 + i * 64 + c0]);
      const ulonglong2 wB = *reinterpret_cast<const ulonglong2*>(&s[OFF_W2 + i * 64 + c0 + 4]);
      const float* xr = &s[OFF_XT + i * ROWS + lane];
      #pragma unroll
      for (int p = 0; p < PTS; ++p) {
        const float a = xr[p * 32];
        const u64 aa = pack2(a, a);
        acc[p][0] = ffma2(wA.x, aa, acc[p][0]);
        acc[p][1] = ffma2(wA.y, aa, acc[p][1]);
        acc[p][2] = ffma2(wB.x, aa, acc[p][2]);
        acc[p][3] = ffma2(wB.y, aa, acc[p][3]);
      }
    }
  }
  __syncthreads();   // retire all xT/w2 reads before hT overwrites region R

  // deferred store of raw h (transposed) into union region
  {
    const int c0 = warp * 8;
    #pragma unroll
    for (int p = 0; p < PTS; ++p) {
      #pragma unroll
      for (int c = 0; c < 4; ++c) {
        float a, b; unpack2(acc[p][c], a, b);
        s[OFF_HT + (c0 + 2 * c) * ROWS + p * 32 + lane]     = a;
        s[OFF_HT + (c0 + 2 * c + 1) * ROWS + p * 32 + lane] = b;
      }
    }
  }
  __syncthreads();

  // ========== LN(64) + relu, thread = row, in place on hT ==========
  {
    float v[64];
    float sm = 0.f;
    #pragma unroll
    for (int i = 0; i < 64; ++i) { v[i] = s[OFF_HT + i * ROWS + tid]; sm += v[i]; }
    const float mu = sm * (1.f / 64.f);
    float vs = 0.f;
    #pragma unroll
    for (int i = 0; i < 64; ++i) { const float d = v[i] - mu; vs += d * d; }
    const float inv = rsqrtf(vs * (1.f / 64.f) + 1e-5f);
    #pragma unroll
    for (int i = 0; i < 64; ++i)
      s[OFF_HT + i * ROWS + tid] =
          fmaxf(0.f, (v[i] - mu) * inv * s[OFF_G2 + i] + s[OFF_BE2 + i]);
  }
  __syncthreads();

  // ===== layer 3 (block-coop) + max over K (butterfly) =====
  {
    const int c0 = warp * 8;
    u64 bp[4];
    #pragma unroll
    for (int c = 0; c < 4; ++c)
      bp[c] = *reinterpret_cast<const u64*>(&s[OFF_B3 + c0 + 2 * c]);
    #pragma unroll
    for (int p = 0; p < PTS; ++p)
      #pragma unroll
      for (int c = 0; c < 4; ++c) acc[p][c] = bp[c];

    #pragma unroll
    for (int i = 0; i < 64; ++i) {
      const ulonglong2 wA = *reinterpret_cast<const ulonglong2*>(&s[OFF_W3 + i * 64 + c0]);
      const ulonglong2 wB = *reinterpret_cast<const ulonglong2*>(&s[OFF_W3 + i * 64 + c0 + 4]);
      const float* hr = &s[OFF_HT + i * ROWS + lane];
      #pragma unroll
      for (int p = 0; p < PTS; ++p) {
        const float a = hr[p * 32];
        const u64 aa = pack2(a, a);
        acc[p][0] = ffma2(wA.x, aa, acc[p][0]);
        acc[p][1] = ffma2(wA.y, aa, acc[p][1]);
        acc[p][2] = ffma2(wB.x, aa, acc[p][2]);
        acc[p][3] = ffma2(wB.y, aa, acc[p][3]);
      }
    }
    #pragma unroll
    for (int p = 0; p < PTS; ++p) {
      float m[8];
      #pragma unroll
      for (int c = 0; c < 4; ++c) unpack2(acc[p][c], m[2 * c], m[2 * c + 1]);
      #pragma unroll
      for (int off = 16; off > 0; off >>= 1) {
        #pragma unroll
        for (int c = 0; c < 8; ++c)
          m[c] = fmaxf(m[c], __shfl_xor_sync(0xffffffffu, m[c], off));
      }
      #pragma unroll
      for (int c = 0; c < 8; ++c)
        if (lane == c) s[OFF_CTR + p * 64 + c0 + c] = m[c];
    }
  }
  __syncthreads();

  // ==== layer 4: warp = point; lane = 4 cols; ow streamed from L2; LN(128) ====
  {
    const float* ctr = &s[OFF_CTR + warp * 64];
    float4 a = *reinterpret_cast<const float4*>(&s[OFF_OB + 4 * lane]);
    #pragma unroll
    for (int i = 0; i < 64; ++i) {
      const float c = ctr[i];
      const float4 w = *reinterpret_cast<const float4*>(&ow[i * 128 + 4 * lane]);
      a.x += c * w.x; a.y += c * w.y; a.z += c * w.z; a.w += c * w.w;
    }
    const float sm = wsum(a.x + a.y + a.z + a.w);
    const float mu = sm * (1.f / 128.f);
    const float dx = a.x - mu, dy = a.y - mu, dz = a.z - mu, dw = a.w - mu;
    const float vs = wsum(dx * dx + dy * dy + dz * dz + dw * dw);
    const float inv = rsqrtf(vs * (1.f / 128.f) + 1e-5f);
    const float4 g  = *reinterpret_cast<const float4*>(&s[OFF_LG + 4 * lane]);
    const float4 bb = *reinterpret_cast<const float4*>(&s[OFF_LB + 4 * lane]);
    float4 o;
    o.x = dx * inv * g.x + bb.x;
    o.y = dy * inv * g.y + bb.y;
    o.z = dz * inv * g.z + bb.z;
    o.w = dw * inv * g.w + bb.w;
    *reinterpret_cast<float4*>(&out[(size_t)point * 128 + 4 * lane]) = o;
  }
}

extern "C" void kernel_launch(void* const* d_in, const int* in_sizes, int n_in,
                              void* d_out, int out_size) {
  const float* pts = (const float*)d_in[0];
  const float* nbr = (const float*)d_in[1];
  const float* w1  = (const float*)d_in[2];
  const float* b1  = (const float*)d_in[3];
  const float* g1  = (const float*)d_in[4];
  const float* be1 = (const float*)d_in[5];
  const float* w2  = (const float*)d_in[6];
  const float* b2  = (const float*)d_in[7];
  const float* g2  = (const float*)d_in[8];
  const float* be2 = (const float*)d_in[9];
  const float* w3  = (const float*)d_in[10];
  const float* b3  = (const float*)d_in[11];
  const float* ow  = (const float*)d_in[12];
  const float* ob  = (const float*)d_in[13];
  const float* lg  = (const float*)d_in[14];
  const float* lb  = (const float*)d_in[15];

  const int P = in_sizes[1] / 96;          // B*N points
  const int grid = P / PTS;                // 4096

  cudaFuncSetAttribute(so3conv_kernel,
                       cudaFuncAttributeMaxDynamicSharedMemorySize,
                       (int)(SMEM_FLOATS * sizeof(float)));
  so3conv_kernel<<<grid, THREADS, SMEM_FLOATS * sizeof(float)>>>(
      pts, nbr, w1, b1, g1, be1, w2, b2, g2, be2, w3, b3,
      ow, ob, lg, lb, (float*)d_out);
}

// round 6
// speedup vs baseline: 1.6657x; 1.2439x over previous
#include <cuda_runtime.h>

#define THREADS 256
#define WARPS 8
#define PTS 8            // points per block
#define ROWS 256         // PTS * 32 neighbor rows
#define CTRS 72          // ctr row stride (16B-aligned, conflict-free for 4 writers)

typedef unsigned long long u64;

// ---- shared memory layout (floats), phase-unioned ----
// R region (16384 floats = 64KB):
//   phase A/B:  w2 = R[0 .. 2048),  xT = R[2048 .. 10240)
//   phase C:    hT = R[0 .. 16384)            (hT[feat][row], stride 256)
#define OFF_W2     0
#define OFF_XT     2048
#define OFF_HT     0
#define OFF_W3     16384
#define OFF_W1     (OFF_W3 + 4096)
#define OFF_B1     (OFF_W1 + 192)
#define OFF_G1     (OFF_B1 + 32)
#define OFF_BE1    (OFF_G1 + 32)
#define OFF_B2     (OFF_BE1 + 32)
#define OFF_G2     (OFF_B2 + 64)
#define OFF_BE2    (OFF_G2 + 64)
#define OFF_B3     (OFF_BE2 + 64)
#define OFF_OB     (OFF_B3 + 64)
#define OFF_LG     (OFF_OB + 128)
#define OFF_LB     (OFF_LG + 128)
#define OFF_CTR    (OFF_LB + 128)
#define SMEM_FLOATS (OFF_CTR + PTS * CTRS)

__device__ __forceinline__ u64 pack2(float x, float y) {
  u64 r; asm("mov.b64 %0, {%1, %2};" : "=l"(r) : "f"(x), "f"(y)); return r;
}
__device__ __forceinline__ void unpack2(u64 v, float &x, float &y) {
  asm("mov.b64 {%0, %1}, %2;" : "=f"(x), "=f"(y) : "l"(v));
}
// Packed 2xfp32 FMA (sm_100+).
__device__ __forceinline__ u64 ffma2(u64 a, u64 b, u64 c) {
  u64 d; asm("fma.rn.f32x2 %0, %1, %2, %3;" : "=l"(d) : "l"(a), "l"(b), "l"(c));
  return d;
}

__device__ __forceinline__ float wsum(float v) {
  #pragma unroll
  for (int o = 16; o > 0; o >>= 1) v += __shfl_xor_sync(0xffffffffu, v, o);
  return v;
}

__device__ __forceinline__ void cpy(float* d, const float* s, int n) {
  for (int i = threadIdx.x; i < n; i += THREADS) d[i] = s[i];
}

extern "C" __global__ void __launch_bounds__(THREADS, 2)
so3conv_kernel(const float* __restrict__ pts, const float* __restrict__ nbr,
               const float* __restrict__ w1, const float* __restrict__ b1,
               const float* __restrict__ g1, const float* __restrict__ be1,
               const float* __restrict__ w2, const float* __restrict__ b2,
               const float* __restrict__ g2, const float* __restrict__ be2,
               const float* __restrict__ w3, const float* __restrict__ b3,
               const float* __restrict__ ow, const float* __restrict__ ob,
               const float* __restrict__ lg, const float* __restrict__ lb,
               float* __restrict__ out)
{
  extern __shared__ float s[];
  cpy(s + OFF_W2, w2, 32 * 64);
  cpy(s + OFF_W3, w3, 64 * 64);
  cpy(s + OFF_W1, w1, 6 * 32);
  cpy(s + OFF_B1, b1, 32); cpy(s + OFF_G1, g1, 32); cpy(s + OFF_BE1, be1, 32);
  cpy(s + OFF_B2, b2, 64); cpy(s + OFF_G2, g2, 64); cpy(s + OFF_BE2, be2, 64);
  cpy(s + OFF_B3, b3, 64);
  cpy(s + OFF_OB, ob, 128); cpy(s + OFF_LG, lg, 128); cpy(s + OFF_LB, lb, 128);
  __syncthreads();

  const int tid  = threadIdx.x;
  const int warp = tid >> 5;
  const int lane = tid & 31;
  const int point = blockIdx.x * PTS + warp;

  // GEMM warp tiling: 2 row-blocks x 4 col-blocks of (128 rows x 16 cols)
  const int r0 = (warp >> 2) * 128;      // row-block base
  const int c0 = (warp & 3) * 16;        // col-block base
  const int ra = r0 + 4 * lane;          // this thread's 4 rows: ra..ra+3

  // ================= rifeat (warp = point, lane = neighbor) =================
  const float px = pts[point * 3 + 0];
  const float py = pts[point * 3 + 1];
  const float pz = pts[point * 3 + 2];
  const float* nb = nbr + (size_t)point * 96 + lane * 3;
  const float nx = nb[0], ny = nb[1], nz = nb[2];

  const float mx = wsum(nx) * 0.03125f;
  const float my = wsum(ny) * 0.03125f;
  const float mz = wsum(nz) * 0.03125f;

  const float l1x = mx - nx, l1y = my - ny, l1z = mz - nz;
  const float l2x = nx - px, l2y = ny - py, l2z = nz - pz;
  const float l3x = px - mx, l3y = py - my, l3z = pz - mz;
  const float n1 = sqrtf(l1x * l1x + l1y * l1y + l1z * l1z);
  const float n2 = sqrtf(l2x * l2x + l2y * l2y + l2z * l2z);
  const float n3 = sqrtf(l3x * l3x + l3y * l3y + l3z * l3z);
  const float d12 = l1x * l2x + l1y * l2y + l1z * l2z;
  const float d23 = l2x * l3x + l2y * l3y + l2z * l3z;
  const float d31 = l3x * l1x + l3y * l1y + l3z * l1z;
  float f[6];
  f[0] = n1; f[1] = n2; f[2] = n3;
  f[3] = d12 / (n1 * n2 + 1e-7f);
  f[4] = d23 / (n2 * n3 + 1e-7f);
  f[5] = d31 / (n3 * n1 + 1e-7f);

  // ========== layer 1: [6]@[6,32] + b1, LN(32) lane-local, relu ==========
  {
    float x[32];
    #pragma unroll
    for (int j = 0; j < 32; ++j) x[j] = s[OFF_B1 + j];
    #pragma unroll
    for (int i = 0; i < 6; ++i) {
      const float a = f[i];
      #pragma unroll
      for (int j = 0; j < 32; ++j) x[j] += a * s[OFF_W1 + i * 32 + j];
    }
    float sm = 0.f;
    #pragma unroll
    for (int j = 0; j < 32; ++j) sm += x[j];
    const float mu = sm * (1.f / 32.f);
    float vs = 0.f;
    #pragma unroll
    for (int j = 0; j < 32; ++j) { const float d = x[j] - mu; vs += d * d; }
    const float inv = rsqrtf(vs * (1.f / 32.f) + 1e-5f);
    #pragma unroll
    for (int j = 0; j < 32; ++j)
      s[OFF_XT + j * ROWS + tid] =
          fmaxf(0.f, (x[j] - mu) * inv * s[OFF_G1 + j] + s[OFF_BE1 + j]);
  }
  __syncthreads();

  // ===== layer 2: warp tile 128 rows x 16 cols; thread = 4 rows x 16 cols =====
  u64 acc[4][8];   // [row-in-quad][col-pair]
  {
    const ulonglong2 bA = *reinterpret_cast<const ulonglong2*>(&s[OFF_B2 + c0]);
    const ulonglong2 bB = *reinterpret_cast<const ulonglong2*>(&s[OFF_B2 + c0 + 4]);
    const ulonglong2 bC = *reinterpret_cast<const ulonglong2*>(&s[OFF_B2 + c0 + 8]);
    const ulonglong2 bD = *reinterpret_cast<const ulonglong2*>(&s[OFF_B2 + c0 + 12]);
    const u64 bp[8] = {bA.x, bA.y, bB.x, bB.y, bC.x, bC.y, bD.x, bD.y};
    #pragma unroll
    for (int r = 0; r < 4; ++r)
      #pragma unroll
      for (int j = 0; j < 8; ++j) acc[r][j] = bp[j];

    #pragma unroll 8
    for (int k = 0; k < 32; ++k) {
      const float4 a = *reinterpret_cast<const float4*>(&s[OFF_XT + k * ROWS + ra]);
      const ulonglong2 wA = *reinterpret_cast<const ulonglong2*>(&s[OFF_W2 + k * 64 + c0]);
      const ulonglong2 wB = *reinterpret_cast<const ulonglong2*>(&s[OFF_W2 + k * 64 + c0 + 4]);
      const ulonglong2 wC = *reinterpret_cast<const ulonglong2*>(&s[OFF_W2 + k * 64 + c0 + 8]);
      const ulonglong2 wD = *reinterpret_cast<const ulonglong2*>(&s[OFF_W2 + k * 64 + c0 + 12]);
      const u64 wp[8] = {wA.x, wA.y, wB.x, wB.y, wC.x, wC.y, wD.x, wD.y};
      const float ar[4] = {a.x, a.y, a.z, a.w};
      #pragma unroll
      for (int r = 0; r < 4; ++r) {
        const u64 aa = pack2(ar[r], ar[r]);
        #pragma unroll
        for (int j = 0; j < 8; ++j) acc[r][j] = ffma2(wp[j], aa, acc[r][j]);
      }
    }
  }
  __syncthreads();   // retire all xT/w2 reads before hT overwrites region R

  // deferred store of raw h into hT[col][row] (16 conflict-free STS.128)
  {
    #pragma unroll
    for (int j = 0; j < 8; ++j) {
      float l0, h0, l1, h1, l2, h2, l3, h3;
      unpack2(acc[0][j], l0, h0); unpack2(acc[1][j], l1, h1);
      unpack2(acc[2][j], l2, h2); unpack2(acc[3][j], l3, h3);
      float4 vlo = {l0, l1, l2, l3};
      float4 vhi = {h0, h1, h2, h3};
      *reinterpret_cast<float4*>(&s[OFF_HT + (c0 + 2 * j) * ROWS + ra]) = vlo;
      *reinterpret_cast<float4*>(&s[OFF_HT + (c0 + 2 * j + 1) * ROWS + ra]) = vhi;
    }
  }
  __syncthreads();

  // ========== LN(64) + relu, thread = row, in place on hT ==========
  {
    float v[64];
    float sm = 0.f;
    #pragma unroll
    for (int i = 0; i < 64; ++i) { v[i] = s[OFF_HT + i * ROWS + tid]; sm += v[i]; }
    const float mu = sm * (1.f / 64.f);
    float vs = 0.f;
    #pragma unroll
    for (int i = 0; i < 64; ++i) { const float d = v[i] - mu; vs += d * d; }
    const float inv = rsqrtf(vs * (1.f / 64.f) + 1e-5f);
    #pragma unroll
    for (int i = 0; i < 64; ++i)
      s[OFF_HT + i * ROWS + tid] =
          fmaxf(0.f, (v[i] - mu) * inv * s[OFF_G2 + i] + s[OFF_BE2 + i]);
  }
  __syncthreads();

  // ===== layer 3: same tiling; then max over 4 local rows + 8-lane butterfly =====
  {
    const ulonglong2 bA = *reinterpret_cast<const ulonglong2*>(&s[OFF_B3 + c0]);
    const ulonglong2 bB = *reinterpret_cast<const ulonglong2*>(&s[OFF_B3 + c0 + 4]);
    const ulonglong2 bC = *reinterpret_cast<const ulonglong2*>(&s[OFF_B3 + c0 + 8]);
    const ulonglong2 bD = *reinterpret_cast<const ulonglong2*>(&s[OFF_B3 + c0 + 12]);
    const u64 bp[8] = {bA.x, bA.y, bB.x, bB.y, bC.x, bC.y, bD.x, bD.y};
    #pragma unroll
    for (int r = 0; r < 4; ++r)
      #pragma unroll
      for (int j = 0; j < 8; ++j) acc[r][j] = bp[j];

    #pragma unroll 8
    for (int k = 0; k < 64; ++k) {
      const float4 a = *reinterpret_cast<const float4*>(&s[OFF_HT + k * ROWS + ra]);
      const ulonglong2 wA = *reinterpret_cast<const ulonglong2*>(&s[OFF_W3 + k * 64 + c0]);
      const ulonglong2 wB = *reinterpret_cast<const ulonglong2*>(&s[OFF_W3 + k * 64 + c0 + 4]);
      const ulonglong2 wC = *reinterpret_cast<const ulonglong2*>(&s[OFF_W3 + k * 64 + c0 + 8]);
      const ulonglong2 wD = *reinterpret_cast<const ulonglong2*>(&s[OFF_W3 + k * 64 + c0 + 12]);
      const u64 wp[8] = {wA.x, wA.y, wB.x, wB.y, wC.x, wC.y, wD.x, wD.y};
      const float ar[4] = {a.x, a.y, a.z, a.w};
      #pragma unroll
      for (int r = 0; r < 4; ++r) {
        const u64 aa = pack2(ar[r], ar[r]);
        #pragma unroll
        for (int j = 0; j < 8; ++j) acc[r][j] = ffma2(wp[j], aa, acc[r][j]);
      }
    }

    // thread-local max over its 4 rows (all same point: rows 4*lane..4*lane+3)
    float m[16];
    #pragma unroll
    for (int j = 0; j < 8; ++j) {
      float l0, h0, l1, h1, l2, h2, l3, h3;
      unpack2(acc[0][j], l0, h0); unpack2(acc[1][j], l1, h1);
      unpack2(acc[2][j], l2, h2); unpack2(acc[3][j], l3, h3);
      m[2 * j]     = fmaxf(fmaxf(l0, l1), fmaxf(l2, l3));
      m[2 * j + 1] = fmaxf(fmaxf(h0, h1), fmaxf(h2, h3));
    }
    // butterfly within 8-lane groups (32 rows = 1 point = 8 threads)
    #pragma unroll
    for (int off = 1; off <= 4; off <<= 1) {
      #pragma unroll
      for (int j = 0; j < 16; ++j)
        m[j] = fmaxf(m[j], __shfl_xor_sync(0xffffffffu, m[j], off));
    }
    if ((lane & 7) == 0) {
      const int pp = (r0 >> 5) + (lane >> 3);   // point index within block
      float* dst = &s[OFF_CTR + pp * CTRS + c0];
      float4 v0 = {m[0], m[1], m[2], m[3]};
      float4 v1 = {m[4], m[5], m[6], m[7]};
      float4 v2 = {m[8], m[9], m[10], m[11]};
      float4 v3 = {m[12], m[13], m[14], m[15]};
      *reinterpret_cast<float4*>(dst)     = v0;
      *reinterpret_cast<float4*>(dst + 4) = v1;
      *reinterpret_cast<float4*>(dst + 8) = v2;
      *reinterpret_cast<float4*>(dst + 12) = v3;
    }
  }
  __syncthreads();

  // ==== layer 4: warp = point; lane = 4 cols; ow streamed from L2; LN(128) ====
  {
    const float* ctr = &s[OFF_CTR + warp * CTRS];
    float4 a = *reinterpret_cast<const float4*>(&s[OFF_OB + 4 * lane]);
    #pragma unroll
    for (int i = 0; i < 64; ++i) {
      const float c = ctr[i];
      const float4 w = *reinterpret_cast<const float4*>(&ow[i * 128 + 4 * lane]);
      a.x += c * w.x; a.y += c * w.y; a.z += c * w.z; a.w += c * w.w;
    }
    const float sm = wsum(a.x + a.y + a.z + a.w);
    const float mu = sm * (1.f / 128.f);
    const float dx = a.x - mu, dy = a.y - mu, dz = a.z - mu, dw = a.w - mu;
    const float vs = wsum(dx * dx + dy * dy + dz * dz + dw * dw);
    const float inv = rsqrtf(vs * (1.f / 128.f) + 1e-5f);
    const float4 g  = *reinterpret_cast<const float4*>(&s[OFF_LG + 4 * lane]);
    const float4 bb = *reinterpret_cast<const float4*>(&s[OFF_LB + 4 * lane]);
    float4 o;
    o.x = dx * inv * g.x + bb.x;
    o.y = dy * inv * g.y + bb.y;
    o.z = dz * inv * g.z + bb.z;
    o.w = dw * inv * g.w + bb.w;
    *reinterpret_cast<float4*>(&out[(size_t)point * 128 + 4 * lane]) = o;
  }
}

extern "C" void kernel_launch(void* const* d_in, const int* in_sizes, int n_in,
                              void* d_out, int out_size) {
  const float* pts = (const float*)d_in[0];
  const float* nbr = (const float*)d_in[1];
  const float* w1  = (const float*)d_in[2];
  const float* b1  = (const float*)d_in[3];
  const float* g1  = (const float*)d_in[4];
  const float* be1 = (const float*)d_in[5];
  const float* w2  = (const float*)d_in[6];
  const float* b2  = (const float*)d_in[7];
  const float* g2  = (const float*)d_in[8];
  const float* be2 = (const float*)d_in[9];
  const float* w3  = (const float*)d_in[10];
  const float* b3  = (const float*)d_in[11];
  const float* ow  = (const float*)d_in[12];
  const float* ob  = (const float*)d_in[13];
  const float* lg  = (const float*)d_in[14];
  const float* lb  = (const float*)d_in[15];

  const int P = in_sizes[1] / 96;          // B*N points
  const int grid = P / PTS;                // 4096

  cudaFuncSetAttribute(so3conv_kernel,
                       cudaFuncAttributeMaxDynamicSharedMemorySize,
                       (int)(SMEM_FLOATS * sizeof(float)));
  so3conv_kernel<<<grid, THREADS, SMEM_FLOATS * sizeof(float)>>>(
      pts, nbr, w1, b1, g1, be1, w2, b2, g2, be2, w3, b3,
      ow, ob, lg, lb, (float*)d_out);
}

// round 7
// speedup vs baseline: 1.9737x; 1.1849x over previous
#include <cuda_runtime.h>

#define THREADS 256
#define PTS 8            // points per block (8 warps, warp = point for M-tiles)
#define XS 36            // x row stride (floats): bank(4*row + t4) conflict-free
#define HS 68            // h row stride: 68%32=4, same property
#define WS 72            // weight row stride: 72%32=8 -> bank(8*t4+g) conflict-free
#define CTR_S 72

// ---- shared memory layout (floats), phase-unioned ----
// union region: phase1 x[256][36] (9216), phase2 h[256][68] (17408)
#define OFF_HX   0
#define OFF_W2   (256 * HS)              // w2 [32][72]
#define OFF_W3   (OFF_W2 + 32 * WS)      // w3 [64][72]
#define OFF_W1   (OFF_W3 + 64 * WS)
#define OFF_B1   (OFF_W1 + 192)
#define OFF_G1   (OFF_B1 + 32)
#define OFF_BE1  (OFF_G1 + 32)
#define OFF_B2   (OFF_BE1 + 32)
#define OFF_G2   (OFF_B2 + 64)
#define OFF_BE2  (OFF_G2 + 64)
#define OFF_B3   (OFF_BE2 + 64)
#define OFF_OB   (OFF_B3 + 64)
#define OFF_LG   (OFF_OB + 128)
#define OFF_LB   (OFF_LG + 128)
#define OFF_CTR  (OFF_LB + 128)
#define SMEM_FLOATS (OFF_CTR + PTS * CTR_S)

__device__ __forceinline__ float wsum(float v) {
  #pragma unroll
  for (int o = 16; o > 0; o >>= 1) v += __shfl_xor_sync(0xffffffffu, v, o);
  return v;
}

__device__ __forceinline__ unsigned tf32_hi(float v) {
  unsigned r; asm("cvt.rna.tf32.f32 %0, %1;" : "=r"(r) : "f"(v)); return r;
}
__device__ __forceinline__ void tf32_split(float v, unsigned &hi, unsigned &lo) {
  hi = tf32_hi(v);
  lo = tf32_hi(v - __uint_as_float(hi));
}

__device__ __forceinline__ void mma8(float c[4], const unsigned a[4], const unsigned b[2]) {
  asm("mma.sync.aligned.m16n8k8.row.col.f32.tf32.tf32.f32 "
      "{%0,%1,%2,%3}, {%4,%5,%6,%7}, {%8,%9}, {%0,%1,%2,%3};"
      : "+f"(c[0]), "+f"(c[1]), "+f"(c[2]), "+f"(c[3])
      : "r"(a[0]), "r"(a[1]), "r"(a[2]), "r"(a[3]), "r"(b[0]), "r"(b[1]));
}

// Warp GEMM: C[256-row slice mb..mb+31][64] += A[.,K] @ B[K,64], fp32 via tf32 3-term split.
// A: sA[row*as + k], B: sB[k*WS + n]. KT = K/8 k-tiles.
template<int KT>
__device__ __forceinline__ void gemm_tf32(const float* __restrict__ sA, int as,
                                          const float* __restrict__ sB,
                                          int mb, int g, int t4,
                                          float C[2][8][4])
{
  #pragma unroll
  for (int kt = 0; kt < KT; ++kt) {
    const int k = 8 * kt + t4;
    unsigned ahi[2][4], alo[2][4];
    #pragma unroll
    for (int mt = 0; mt < 2; ++mt) {
      const int r = mb + 16 * mt + g;
      const float a0 = sA[r * as + k];
      const float a1 = sA[(r + 8) * as + k];
      const float a2 = sA[r * as + k + 4];
      const float a3 = sA[(r + 8) * as + k + 4];
      tf32_split(a0, ahi[mt][0], alo[mt][0]);
      tf32_split(a1, ahi[mt][1], alo[mt][1]);
      tf32_split(a2, ahi[mt][2], alo[mt][2]);
      tf32_split(a3, ahi[mt][3], alo[mt][3]);
    }
    #pragma unroll
    for (int nh = 0; nh < 2; ++nh) {
      unsigned bhi[4][2], blo[4][2];
      #pragma unroll
      for (int nt = 0; nt < 4; ++nt) {
        const int n = 8 * (4 * nh + nt) + g;
        const float b0 = sB[k * WS + n];
        const float b1 = sB[(k + 4) * WS + n];
        tf32_split(b0, bhi[nt][0], blo[nt][0]);
        tf32_split(b1, bhi[nt][1], blo[nt][1]);
      }
      #pragma unroll
      for (int mt = 0; mt < 2; ++mt)
        #pragma unroll
        for (int nt = 0; nt < 4; ++nt) {
          float* c = C[mt][4 * nh + nt];
          mma8(c, ahi[mt], bhi[nt]);
          mma8(c, ahi[mt], blo[nt]);
          mma8(c, alo[mt], bhi[nt]);
        }
    }
  }
}

extern "C" __global__ void __launch_bounds__(THREADS, 2)
so3conv_kernel(const float* __restrict__ pts, const float* __restrict__ nbr,
               const float* __restrict__ w1, const float* __restrict__ b1,
               const float* __restrict__ g1, const float* __restrict__ be1,
               const float* __restrict__ w2, const float* __restrict__ b2,
               const float* __restrict__ g2, const float* __restrict__ be2,
               const float* __restrict__ w3, const float* __restrict__ b3,
               const float* __restrict__ ow, const float* __restrict__ ob,
               const float* __restrict__ lg, const float* __restrict__ lb,
               float* __restrict__ out)
{
  extern __shared__ float s[];
  const int tid  = threadIdx.x;
  // strided weight copies (row stride WS)
  for (int i = tid; i < 32 * 64; i += THREADS) s[OFF_W2 + (i >> 6) * WS + (i & 63)] = w2[i];
  for (int i = tid; i < 64 * 64; i += THREADS) s[OFF_W3 + (i >> 6) * WS + (i & 63)] = w3[i];
  for (int i = tid; i < 192; i += THREADS) s[OFF_W1 + i] = w1[i];
  if (tid < 32) { s[OFF_B1 + tid] = b1[tid]; s[OFF_G1 + tid] = g1[tid]; s[OFF_BE1 + tid] = be1[tid]; }
  if (tid < 64) { s[OFF_B2 + tid] = b2[tid]; s[OFF_G2 + tid] = g2[tid]; s[OFF_BE2 + tid] = be2[tid]; s[OFF_B3 + tid] = b3[tid]; }
  if (tid < 128) { s[OFF_OB + tid] = ob[tid]; s[OFF_LG + tid] = lg[tid]; s[OFF_LB + tid] = lb[tid]; }

  const int warp = tid >> 5;
  const int lane = tid & 31;
  const int g  = lane >> 2;    // mma groupID
  const int t4 = lane & 3;     // mma threadID-in-group
  const int mb = warp * 32;    // warp's 32 rows == its point's rows
  const int point = blockIdx.x * PTS + warp;

  // ================= rifeat (warp = point, lane = neighbor) =================
  const float px = pts[point * 3 + 0];
  const float py = pts[point * 3 + 1];
  const float pz = pts[point * 3 + 2];
  const float* nb = nbr + (size_t)point * 96 + lane * 3;
  const float nx = nb[0], ny = nb[1], nz = nb[2];

  const float mx = wsum(nx) * 0.03125f;
  const float my = wsum(ny) * 0.03125f;
  const float mz = wsum(nz) * 0.03125f;

  const float l1x = mx - nx, l1y = my - ny, l1z = mz - nz;
  const float l2x = nx - px, l2y = ny - py, l2z = nz - pz;
  const float l3x = px - mx, l3y = py - my, l3z = pz - mz;
  const float n1 = sqrtf(l1x * l1x + l1y * l1y + l1z * l1z);
  const float n2 = sqrtf(l2x * l2x + l2y * l2y + l2z * l2z);
  const float n3 = sqrtf(l3x * l3x + l3y * l3y + l3z * l3z);
  const float d12 = l1x * l2x + l1y * l2y + l1z * l2z;
  const float d23 = l2x * l3x + l2y * l3y + l2z * l3z;
  const float d31 = l3x * l1x + l3y * l1y + l3z * l1z;
  float f[6];
  f[0] = n1; f[1] = n2; f[2] = n3;
  f[3] = d12 / (n1 * n2 + 1e-7f);
  f[4] = d23 / (n2 * n3 + 1e-7f);
  f[5] = d31 / (n3 * n1 + 1e-7f);

  __syncthreads();   // weight staging complete

  // ========== layer 1: [6]@[6,32] + b1, LN(32) lane-local, relu -> x[tid][36] ==========
  {
    float x[32];
    #pragma unroll
    for (int j = 0; j < 32; ++j) x[j] = s[OFF_B1 + j];
    #pragma unroll
    for (int i = 0; i < 6; ++i) {
      const float a = f[i];
      #pragma unroll
      for (int j = 0; j < 32; ++j) x[j] += a * s[OFF_W1 + i * 32 + j];
    }
    float sm = 0.f;
    #pragma unroll
    for (int j = 0; j < 32; ++j) sm += x[j];
    const float mu = sm * (1.f / 32.f);
    float vs = 0.f;
    #pragma unroll
    for (int j = 0; j < 32; ++j) { const float d = x[j] - mu; vs += d * d; }
    const float inv = rsqrtf(vs * (1.f / 32.f) + 1e-5f);
    #pragma unroll
    for (int j = 0; j < 32; ++j)
      x[j] = fmaxf(0.f, (x[j] - mu) * inv * s[OFF_G1 + j] + s[OFF_BE1 + j]);
    #pragma unroll
    for (int q = 0; q < 8; ++q)
      *reinterpret_cast<float4*>(&s[OFF_HX + tid * XS + 4 * q]) =
          make_float4(x[4 * q], x[4 * q + 1], x[4 * q + 2], x[4 * q + 3]);
  }
  __syncthreads();

  // ===== layer 2: tensor GEMM [32 rows x 64 cols], K=32 =====
  float C[2][8][4];
  #pragma unroll
  for (int nt = 0; nt < 8; ++nt) {
    const float2 b = *reinterpret_cast<const float2*>(&s[OFF_B2 + 8 * nt + 2 * t4]);
    C[0][nt][0] = b.x; C[0][nt][1] = b.y; C[0][nt][2] = b.x; C[0][nt][3] = b.y;
    C[1][nt][0] = b.x; C[1][nt][1] = b.y; C[1][nt][2] = b.x; C[1][nt][3] = b.y;
  }
  gemm_tf32<4>(s + OFF_HX, XS, s + OFF_W2, mb, g, t4, C);

  // ---- LN(64) + relu fully in registers (quad shuffles) ----
  {
    float mu[4], inv[4];
    float sm[4] = {0.f, 0.f, 0.f, 0.f};
    #pragma unroll
    for (int nt = 0; nt < 8; ++nt) {
      sm[0] += C[0][nt][0] + C[0][nt][1];
      sm[1] += C[0][nt][2] + C[0][nt][3];
      sm[2] += C[1][nt][0] + C[1][nt][1];
      sm[3] += C[1][nt][2] + C[1][nt][3];
    }
    #pragma unroll
    for (int r = 0; r < 4; ++r) {
      sm[r] += __shfl_xor_sync(0xffffffffu, sm[r], 1);
      sm[r] += __shfl_xor_sync(0xffffffffu, sm[r], 2);
      mu[r] = sm[r] * (1.f / 64.f);
    }
    float vs[4] = {0.f, 0.f, 0.f, 0.f};
    #pragma unroll
    for (int nt = 0; nt < 8; ++nt) {
      float d;
      d = C[0][nt][0] - mu[0]; vs[0] += d * d;
      d = C[0][nt][1] - mu[0]; vs[0] += d * d;
      d = C[0][nt][2] - mu[1]; vs[1] += d * d;
      d = C[0][nt][3] - mu[1]; vs[1] += d * d;
      d = C[1][nt][0] - mu[2]; vs[2] += d * d;
      d = C[1][nt][1] - mu[2]; vs[2] += d * d;
      d = C[1][nt][2] - mu[3]; vs[3] += d * d;
      d = C[1][nt][3] - mu[3]; vs[3] += d * d;
    }
    #pragma unroll
    for (int r = 0; r < 4; ++r) {
      vs[r] += __shfl_xor_sync(0xffffffffu, vs[r], 1);
      vs[r] += __shfl_xor_sync(0xffffffffu, vs[r], 2);
      inv[r] = rsqrtf(vs[r] * (1.f / 64.f) + 1e-5f);
    }
    #pragma unroll
    for (int nt = 0; nt < 8; ++nt) {
      const float2 gg = *reinterpret_cast<const float2*>(&s[OFF_G2 + 8 * nt + 2 * t4]);
      const float2 bb = *reinterpret_cast<const float2*>(&s[OFF_BE2 + 8 * nt + 2 * t4]);
      C[0][nt][0] = fmaxf(0.f, (C[0][nt][0] - mu[0]) * inv[0] * gg.x + bb.x);
      C[0][nt][1] = fmaxf(0.f, (C[0][nt][1] - mu[0]) * inv[0] * gg.y + bb.y);
      C[0][nt][2] = fmaxf(0.f, (C[0][nt][2] - mu[1]) * inv[1] * gg.x + bb.x);
      C[0][nt][3] = fmaxf(0.f, (C[0][nt][3] - mu[1]) * inv[1] * gg.y + bb.y);
      C[1][nt][0] = fmaxf(0.f, (C[1][nt][0] - mu[2]) * inv[2] * gg.x + bb.x);
      C[1][nt][1] = fmaxf(0.f, (C[1][nt][1] - mu[2]) * inv[2] * gg.y + bb.y);
      C[1][nt][2] = fmaxf(0.f, (C[1][nt][2] - mu[3]) * inv[3] * gg.x + bb.x);
      C[1][nt][3] = fmaxf(0.f, (C[1][nt][3] - mu[3]) * inv[3] * gg.y + bb.y);
    }
  }
  __syncthreads();   // all x reads retired before h overwrites the union region

  // store h [row][HS]
  #pragma unroll
  for (int mt = 0; mt < 2; ++mt) {
    const int r = mb + 16 * mt + g;
    #pragma unroll
    for (int nt = 0; nt < 8; ++nt) {
      const int cc = 8 * nt + 2 * t4;
      *reinterpret_cast<float2*>(&s[OFF_HX + r * HS + cc]) =
          make_float2(C[mt][nt][0], C[mt][nt][1]);
      *reinterpret_cast<float2*>(&s[OFF_HX + (r + 8) * HS + cc]) =
          make_float2(C[mt][nt][2], C[mt][nt][3]);
    }
  }
  __syncthreads();

  // ===== layer 3: tensor GEMM K=64, then max over the warp's 32 rows =====
  #pragma unroll
  for (int nt = 0; nt < 8; ++nt) {
    const float2 b = *reinterpret_cast<const float2*>(&s[OFF_B3 + 8 * nt + 2 * t4]);
    C[0][nt][0] = b.x; C[0][nt][1] = b.y; C[0][nt][2] = b.x; C[0][nt][3] = b.y;
    C[1][nt][0] = b.x; C[1][nt][1] = b.y; C[1][nt][2] = b.x; C[1][nt][3] = b.y;
  }
  gemm_tf32<8>(s + OFF_HX, HS, s + OFF_W3, mb, g, t4, C);

  {
    float m0[8], m1[8];
    #pragma unroll
    for (int nt = 0; nt < 8; ++nt) {
      m0[nt] = fmaxf(fmaxf(C[0][nt][0], C[0][nt][2]), fmaxf(C[1][nt][0], C[1][nt][2]));
      m1[nt] = fmaxf(fmaxf(C[0][nt][1], C[0][nt][3]), fmaxf(C[1][nt][1], C[1][nt][3]));
    }
    #pragma unroll
    for (int off = 4; off <= 16; off <<= 1) {
      #pragma unroll
      for (int nt = 0; nt < 8; ++nt) {
        m0[nt] = fmaxf(m0[nt], __shfl_xor_sync(0xffffffffu, m0[nt], off));
        m1[nt] = fmaxf(m1[nt], __shfl_xor_sync(0xffffffffu, m1[nt], off));
      }
    }
    if (lane < 4) {   // g == 0 lanes: t4 = 0..3 cover all col groups
      #pragma unroll
      for (int nt = 0; nt < 8; ++nt)
        *reinterpret_cast<float2*>(&s[OFF_CTR + warp * CTR_S + 8 * nt + 2 * t4]) =
            make_float2(m0[nt], m1[nt]);
    }
  }
  __syncthreads();

  // ==== layer 4: warp = point; lane = 4 cols; ow streamed from L2; LN(128) ====
  {
    const float* ctr = &s[OFF_CTR + warp * CTR_S];
    float4 a = *reinterpret_cast<const float4*>(&s[OFF_OB + 4 * lane]);
    #pragma unroll
    for (int i = 0; i < 64; ++i) {
      const float c = ctr[i];
      const float4 w = *reinterpret_cast<const float4*>(&ow[i * 128 + 4 * lane]);
      a.x += c * w.x; a.y += c * w.y; a.z += c * w.z; a.w += c * w.w;
    }
    const float sm = wsum(a.x + a.y + a.z + a.w);
    const float mu = sm * (1.f / 128.f);
    const float dx = a.x - mu, dy = a.y - mu, dz = a.z - mu, dw = a.w - mu;
    const float vs = wsum(dx * dx + dy * dy + dz * dz + dw * dw);
    const float inv = rsqrtf(vs * (1.f / 128.f) + 1e-5f);
    const float4 gv = *reinterpret_cast<const float4*>(&s[OFF_LG + 4 * lane]);
    const float4 bv = *reinterpret_cast<const float4*>(&s[OFF_LB + 4 * lane]);
    float4 o;
    o.x = dx * inv * gv.x + bv.x;
    o.y = dy * inv * gv.y + bv.y;
    o.z = dz * inv * gv.z + bv.z;
    o.w = dw * inv * gv.w + bv.w;
    *reinterpret_cast<float4*>(&out[(size_t)point * 128 + 4 * lane]) = o;
  }
}

extern "C" void kernel_launch(void* const* d_in, const int* in_sizes, int n_in,
                              void* d_out, int out_size) {
  const float* pts = (const float*)d_in[0];
  const float* nbr = (const float*)d_in[1];
  const float* w1  = (const float*)d_in[2];
  const float* b1  = (const float*)d_in[3];
  const float* g1  = (const float*)d_in[4];
  const float* be1 = (const float*)d_in[5];
  const float* w2  = (const float*)d_in[6];
  const float* b2  = (const float*)d_in[7];
  const float* g2  = (const float*)d_in[8];
  const float* be2 = (const float*)d_in[9];
  const float* w3  = (const float*)d_in[10];
  const float* b3  = (const float*)d_in[11];
  const float* ow  = (const float*)d_in[12];
  const float* ob  = (const float*)d_in[13];
  const float* lg  = (const float*)d_in[14];
  const float* lb  = (const float*)d_in[15];

  const int P = in_sizes[1] / 96;          // B*N points
  const int grid = P / PTS;                // 4096

  cudaFuncSetAttribute(so3conv_kernel,
                       cudaFuncAttributeMaxDynamicSharedMemorySize,
                       (int)(SMEM_FLOATS * sizeof(float)));
  so3conv_kernel<<<grid, THREADS, SMEM_FLOATS * sizeof(float)>>>(
      pts, nbr, w1, b1, g1, be1, w2, b2, g2, be2, w3, b3,
      ow, ob, lg, lb, (float*)d_out);
}

// round 8
// speedup vs baseline: 2.9113x; 1.4751x over previous
#include <cuda_runtime.h>

#define THREADS 256
#define PTS 8            // points per block (warp = point)
#define XS 20            // x word stride (16 words + 4 pad): bank 20g+t4 conflict-free
#define HS 36            // h word stride (32 words + 4): bank 4g+t4 conflict-free
#define WS 72            // weight word stride: bank 8t4+g conflict-free
#define CTR_S 72

// ---- shared memory (32-bit words), phase-unioned ----
// union: phase1 xhi[256][20]@0, xlo@5120 ; phase2 hhi[256][36]@0, hlo@9216
#define OFF_XHI  0
#define OFF_XLO  5120
#define OFF_HHI  0
#define OFF_HLO  9216
#define OFF_W2H  18432
#define OFF_W2L  (OFF_W2H + 16 * WS)
#define OFF_W3H  (OFF_W2L + 16 * WS)
#define OFF_W3L  (OFF_W3H + 32 * WS)
#define OFF_W1   (OFF_W3L + 32 * WS)
#define OFF_B1   (OFF_W1 + 192)
#define OFF_G1   (OFF_B1 + 32)
#define OFF_BE1  (OFF_G1 + 32)
#define OFF_B2   (OFF_BE1 + 32)
#define OFF_G2   (OFF_B2 + 64)
#define OFF_BE2  (OFF_G2 + 64)
#define OFF_B3   (OFF_BE2 + 64)
#define OFF_OB   (OFF_B3 + 64)
#define OFF_LG   (OFF_OB + 128)
#define OFF_LB   (OFF_LG + 128)
#define OFF_CTR  (OFF_LB + 128)
#define SMEM_FLOATS (OFF_CTR + PTS * CTR_S)

__device__ __forceinline__ float wsum(float v) {
  #pragma unroll
  for (int o = 16; o > 0; o >>= 1) v += __shfl_xor_sync(0xffffffffu, v, o);
  return v;
}

// pack two floats to bf16x2: e0 -> low half (even k), e1 -> high half (odd k)
__device__ __forceinline__ unsigned pack_bf16(float e0, float e1) {
  unsigned r; asm("cvt.rn.bf16x2.f32 %0, %1, %2;" : "=r"(r) : "f"(e1), "f"(e0));
  return r;
}
// split (e0,e1) into bf16 hi word + bf16 lo (residual) word
__device__ __forceinline__ void split_pair(float e0, float e1, unsigned &hi, unsigned &lo) {
  hi = pack_bf16(e0, e1);
  const float h0 = __uint_as_float(hi << 16);
  const float h1 = __uint_as_float(hi & 0xffff0000u);
  lo = pack_bf16(e0 - h0, e1 - h1);
}

__device__ __forceinline__ void mma16(float c[4], const unsigned a[4], const unsigned b[2]) {
  asm("mma.sync.aligned.m16n8k16.row.col.f32.bf16.bf16.f32 "
      "{%0,%1,%2,%3}, {%4,%5,%6,%7}, {%8,%9}, {%0,%1,%2,%3};"
      : "+f"(c[0]), "+f"(c[1]), "+f"(c[2]), "+f"(c[3])
      : "r"(a[0]), "r"(a[1]), "r"(a[2]), "r"(a[3]), "r"(b[0]), "r"(b[1]));
}

// C[warp's 32 rows][64] += A @ B, fp32 accuracy via bf16 3-term split.
// A words: sA*[row*as + j] (word j packs k=2j,2j+1). B words: sB*[j*WS + n].
template<int KT>   // KT = K/16 k-tiles
__device__ __forceinline__ void gemm_bf16(const unsigned* __restrict__ sAhi,
                                          const unsigned* __restrict__ sAlo, int as,
                                          const unsigned* __restrict__ sBhi,
                                          const unsigned* __restrict__ sBlo,
                                          int mb, int g, int t4, float C[2][8][4])
{
  #pragma unroll
  for (int kt = 0; kt < KT; ++kt) {
    const int j0 = 8 * kt + t4;
    unsigned ahi[2][4], alo[2][4];
    #pragma unroll
    for (int mt = 0; mt < 2; ++mt) {
      const int r = mb + 16 * mt + g;
      ahi[mt][0] = sAhi[r * as + j0];           alo[mt][0] = sAlo[r * as + j0];
      ahi[mt][1] = sAhi[(r + 8) * as + j0];     alo[mt][1] = sAlo[(r + 8) * as + j0];
      ahi[mt][2] = sAhi[r * as + j0 + 4];       alo[mt][2] = sAlo[r * as + j0 + 4];
      ahi[mt][3] = sAhi[(r + 8) * as + j0 + 4]; alo[mt][3] = sAlo[(r + 8) * as + j0 + 4];
    }
    #pragma unroll
    for (int nt = 0; nt < 8; ++nt) {
      const int n = 8 * nt + g;
      unsigned bhi[2], blo[2];
      bhi[0] = sBhi[j0 * WS + n]; bhi[1] = sBhi[(j0 + 4) * WS + n];
      blo[0] = sBlo[j0 * WS + n]; blo[1] = sBlo[(j0 + 4) * WS + n];
      #pragma unroll
      for (int mt = 0; mt < 2; ++mt) {
        mma16(C[mt][nt], ahi[mt], bhi);
        mma16(C[mt][nt], ahi[mt], blo);
        mma16(C[mt][nt], alo[mt], bhi);
      }
    }
  }
}

extern "C" __global__ void __launch_bounds__(THREADS, 2)
so3conv_kernel(const float* __restrict__ pts, const float* __restrict__ nbr,
               const float* __restrict__ w1, const float* __restrict__ b1,
               const float* __restrict__ g1, const float* __restrict__ be1,
               const float* __restrict__ w2, const float* __restrict__ b2,
               const float* __restrict__ g2, const float* __restrict__ be2,
               const float* __restrict__ w3, const float* __restrict__ b3,
               const float* __restrict__ ow, const float* __restrict__ ob,
               const float* __restrict__ lg, const float* __restrict__ lb,
               float* __restrict__ out)
{
  extern __shared__ float s[];
  unsigned* su = reinterpret_cast<unsigned*>(s);
  const int tid = threadIdx.x;

  // ---- stage weights, pre-split to bf16 hi/lo packed words ----
  for (int i = tid; i < 16 * 64; i += THREADS) {
    const int j = i >> 6, n = i & 63;
    unsigned hi, lo;
    split_pair(w2[j * 128 + n], w2[j * 128 + 64 + n], hi, lo);
    su[OFF_W2H + j * WS + n] = hi; su[OFF_W2L + j * WS + n] = lo;
  }
  for (int i = tid; i < 32 * 64; i += THREADS) {
    const int j = i >> 6, n = i & 63;
    unsigned hi, lo;
    split_pair(w3[j * 128 + n], w3[j * 128 + 64 + n], hi, lo);
    su[OFF_W3H + j * WS + n] = hi; su[OFF_W3L + j * WS + n] = lo;
  }
  for (int i = tid; i < 192; i += THREADS) s[OFF_W1 + i] = w1[i];
  if (tid < 32) { s[OFF_B1 + tid] = b1[tid]; s[OFF_G1 + tid] = g1[tid]; s[OFF_BE1 + tid] = be1[tid]; }
  if (tid < 64) { s[OFF_B2 + tid] = b2[tid]; s[OFF_G2 + tid] = g2[tid]; s[OFF_BE2 + tid] = be2[tid]; s[OFF_B3 + tid] = b3[tid]; }
  if (tid < 128) { s[OFF_OB + tid] = ob[tid]; s[OFF_LG + tid] = lg[tid]; s[OFF_LB + tid] = lb[tid]; }

  const int warp = tid >> 5;
  const int lane = tid & 31;
  const int g  = lane >> 2;
  const int t4 = lane & 3;
  const int mb = warp * 32;
  const int point = blockIdx.x * PTS + warp;

  // ================= rifeat (warp = point, lane = neighbor) =================
  const float px = pts[point * 3 + 0];
  const float py = pts[point * 3 + 1];
  const float pz = pts[point * 3 + 2];
  const float* nb = nbr + (size_t)point * 96 + lane * 3;
  const float nx = nb[0], ny = nb[1], nz = nb[2];

  const float mx = wsum(nx) * 0.03125f;
  const float my = wsum(ny) * 0.03125f;
  const float mz = wsum(nz) * 0.03125f;

  const float l1x = mx - nx, l1y = my - ny, l1z = mz - nz;
  const float l2x = nx - px, l2y = ny - py, l2z = nz - pz;
  const float l3x = px - mx, l3y = py - my, l3z = pz - mz;
  const float n1 = sqrtf(l1x * l1x + l1y * l1y + l1z * l1z);
  const float n2 = sqrtf(l2x * l2x + l2y * l2y + l2z * l2z);
  const float n3 = sqrtf(l3x * l3x + l3y * l3y + l3z * l3z);
  const float d12 = l1x * l2x + l1y * l2y + l1z * l2z;
  const float d23 = l2x * l3x + l2y * l3y + l2z * l3z;
  const float d31 = l3x * l1x + l3y * l1y + l3z * l1z;
  float f[6];
  f[0] = n1; f[1] = n2; f[2] = n3;
  f[3] = d12 / (n1 * n2 + 1e-7f);
  f[4] = d23 / (n2 * n3 + 1e-7f);
  f[5] = d31 / (n3 * n1 + 1e-7f);

  __syncthreads();   // staging complete

  // ========== layer 1: [6]@[6,32] + b1, LN(32) lane-local, relu -> split x ==========
  {
    float x[32];
    #pragma unroll
    for (int j = 0; j < 32; ++j) x[j] = s[OFF_B1 + j];
    #pragma unroll
    for (int i = 0; i < 6; ++i) {
      const float a = f[i];
      #pragma unroll
      for (int j = 0; j < 32; ++j) x[j] += a * s[OFF_W1 + i * 32 + j];
    }
    float sm = 0.f;
    #pragma unroll
    for (int j = 0; j < 32; ++j) sm += x[j];
    const float mu = sm * (1.f / 32.f);
    float vs = 0.f;
    #pragma unroll
    for (int j = 0; j < 32; ++j) { const float d = x[j] - mu; vs += d * d; }
    const float inv = rsqrtf(vs * (1.f / 32.f) + 1e-5f);
    #pragma unroll
    for (int j = 0; j < 32; ++j)
      x[j] = fmaxf(0.f, (x[j] - mu) * inv * s[OFF_G1 + j] + s[OFF_BE1 + j]);
    #pragma unroll
    for (int q = 0; q < 16; ++q) {
      unsigned hi, lo;
      split_pair(x[2 * q], x[2 * q + 1], hi, lo);
      su[OFF_XHI + tid * XS + q] = hi;
      su[OFF_XLO + tid * XS + q] = lo;
    }
  }
  __syncthreads();

  // ===== layer 2: bf16 tensor GEMM [32 x 64], K=32 (2 k-tiles) =====
  float C[2][8][4];
  #pragma unroll
  for (int nt = 0; nt < 8; ++nt) {
    const float2 b = *reinterpret_cast<const float2*>(&s[OFF_B2 + 8 * nt + 2 * t4]);
    C[0][nt][0] = b.x; C[0][nt][1] = b.y; C[0][nt][2] = b.x; C[0][nt][3] = b.y;
    C[1][nt][0] = b.x; C[1][nt][1] = b.y; C[1][nt][2] = b.x; C[1][nt][3] = b.y;
  }
  gemm_bf16<2>(su + OFF_XHI, su + OFF_XLO, XS, su + OFF_W2H, su + OFF_W2L, mb, g, t4, C);

  // ---- LN(64) + relu fully in registers (quad shuffles) ----
  {
    float mu[4], inv[4];
    float sm[4] = {0.f, 0.f, 0.f, 0.f};
    #pragma unroll
    for (int nt = 0; nt < 8; ++nt) {
      sm[0] += C[0][nt][0] + C[0][nt][1];
      sm[1] += C[0][nt][2] + C[0][nt][3];
      sm[2] += C[1][nt][0] + C[1][nt][1];
      sm[3] += C[1][nt][2] + C[1][nt][3];
    }
    #pragma unroll
    for (int r = 0; r < 4; ++r) {
      sm[r] += __shfl_xor_sync(0xffffffffu, sm[r], 1);
      sm[r] += __shfl_xor_sync(0xffffffffu, sm[r], 2);
      mu[r] = sm[r] * (1.f / 64.f);
    }
    float vs[4] = {0.f, 0.f, 0.f, 0.f};
    #pragma unroll
    for (int nt = 0; nt < 8; ++nt) {
      float d;
      d = C[0][nt][0] - mu[0]; vs[0] += d * d;
      d = C[0][nt][1] - mu[0]; vs[0] += d * d;
      d = C[0][nt][2] - mu[1]; vs[1] += d * d;
      d = C[0][nt][3] - mu[1]; vs[1] += d * d;
      d = C[1][nt][0] - mu[2]; vs[2] += d * d;
      d = C[1][nt][1] - mu[2]; vs[2] += d * d;
      d = C[1][nt][2] - mu[3]; vs[3] += d * d;
      d = C[1][nt][3] - mu[3]; vs[3] += d * d;
    }
    #pragma unroll
    for (int r = 0; r < 4; ++r) {
      vs[r] += __shfl_xor_sync(0xffffffffu, vs[r], 1);
      vs[r] += __shfl_xor_sync(0xffffffffu, vs[r], 2);
      inv[r] = rsqrtf(vs[r] * (1.f / 64.f) + 1e-5f);
    }
    #pragma unroll
    for (int nt = 0; nt < 8; ++nt) {
      const float2 gg = *reinterpret_cast<const float2*>(&s[OFF_G2 + 8 * nt + 2 * t4]);
      const float2 bb = *reinterpret_cast<const float2*>(&s[OFF_BE2 + 8 * nt + 2 * t4]);
      C[0][nt][0] = fmaxf(0.f, (C[0][nt][0] - mu[0]) * inv[0] * gg.x + bb.x);
      C[0][nt][1] = fmaxf(0.f, (C[0][nt][1] - mu[0]) * inv[0] * gg.y + bb.y);
      C[0][nt][2] = fmaxf(0.f, (C[0][nt][2] - mu[1]) * inv[1] * gg.x + bb.x);
      C[0][nt][3] = fmaxf(0.f, (C[0][nt][3] - mu[1]) * inv[1] * gg.y + bb.y);
      C[1][nt][0] = fmaxf(0.f, (C[1][nt][0] - mu[2]) * inv[2] * gg.x + bb.x);
      C[1][nt][1] = fmaxf(0.f, (C[1][nt][1] - mu[2]) * inv[2] * gg.y + bb.y);
      C[1][nt][2] = fmaxf(0.f, (C[1][nt][2] - mu[3]) * inv[3] * gg.x + bb.x);
      C[1][nt][3] = fmaxf(0.f, (C[1][nt][3] - mu[3]) * inv[3] * gg.y + bb.y);
    }
  }
  __syncthreads();   // retire all x reads before h overwrites the union region

  // store h as pre-split bf16 hi/lo words: word (4nt+t4) packs cols (8nt+2t4, +1)
  #pragma unroll
  for (int mt = 0; mt < 2; ++mt) {
    const int r = mb + 16 * mt + g;
    #pragma unroll
    for (int nt = 0; nt < 8; ++nt) {
      const int w = 4 * nt + t4;
      unsigned hi, lo;
      split_pair(C[mt][nt][0], C[mt][nt][1], hi, lo);
      su[OFF_HHI + r * HS + w] = hi; su[OFF_HLO + r * HS + w] = lo;
      split_pair(C[mt][nt][2], C[mt][nt][3], hi, lo);
      su[OFF_HHI + (r + 8) * HS + w] = hi; su[OFF_HLO + (r + 8) * HS + w] = lo;
    }
  }
  __syncthreads();

  // ===== layer 3: bf16 tensor GEMM K=64 (4 k-tiles), then max over 32 rows =====
  #pragma unroll
  for (int nt = 0; nt < 8; ++nt) {
    const float2 b = *reinterpret_cast<const float2*>(&s[OFF_B3 + 8 * nt + 2 * t4]);
    C[0][nt][0] = b.x; C[0][nt][1] = b.y; C[0][nt][2] = b.x; C[0][nt][3] = b.y;
    C[1][nt][0] = b.x; C[1][nt][1] = b.y; C[1][nt][2] = b.x; C[1][nt][3] = b.y;
  }
  gemm_bf16<4>(su + OFF_HHI, su + OFF_HLO, HS, su + OFF_W3H, su + OFF_W3L, mb, g, t4, C);

  {
    float m0[8], m1[8];
    #pragma unroll
    for (int nt = 0; nt < 8; ++nt) {
      m0[nt] = fmaxf(fmaxf(C[0][nt][0], C[0][nt][2]), fmaxf(C[1][nt][0], C[1][nt][2]));
      m1[nt] = fmaxf(fmaxf(C[0][nt][1], C[0][nt][3]), fmaxf(C[1][nt][1], C[1][nt][3]));
    }
    #pragma unroll
    for (int off = 4; off <= 16; off <<= 1) {
      #pragma unroll
      for (int nt = 0; nt < 8; ++nt) {
        m0[nt] = fmaxf(m0[nt], __shfl_xor_sync(0xffffffffu, m0[nt], off));
        m1[nt] = fmaxf(m1[nt], __shfl_xor_sync(0xffffffffu, m1[nt], off));
      }
    }
    if (lane < 4) {   // g==0: t4 covers all column groups
      #pragma unroll
      for (int nt = 0; nt < 8; ++nt)
        *reinterpret_cast<float2*>(&s[OFF_CTR + warp * CTR_S + 8 * nt + 2 * t4]) =
            make_float2(m0[nt], m1[nt]);
    }
  }
  __syncthreads();

  // ==== layer 4: warp = point; lane = 4 cols; ow streamed from L2; LN(128) ====
  {
    const float* ctr = &s[OFF_CTR + warp * CTR_S];
    float4 a = *reinterpret_cast<const float4*>(&s[OFF_OB + 4 * lane]);
    #pragma unroll
    for (int i = 0; i < 64; ++i) {
      const float c = ctr[i];
      const float4 w = *reinterpret_cast<const float4*>(&ow[i * 128 + 4 * lane]);
      a.x += c * w.x; a.y += c * w.y; a.z += c * w.z; a.w += c * w.w;
    }
    const float sm = wsum(a.x + a.y + a.z + a.w);
    const float mu = sm * (1.f / 128.f);
    const float dx = a.x - mu, dy = a.y - mu, dz = a.z - mu, dw = a.w - mu;
    const float vs = wsum(dx * dx + dy * dy + dz * dz + dw * dw);
    const float inv = rsqrtf(vs * (1.f / 128.f) + 1e-5f);
    const float4 gv = *reinterpret_cast<const float4*>(&s[OFF_LG + 4 * lane]);
    const float4 bv = *reinterpret_cast<const float4*>(&s[OFF_LB + 4 * lane]);
    float4 o;
    o.x = dx * inv * gv.x + bv.x;
    o.y = dy * inv * gv.y + bv.y;
    o.z = dz * inv * gv.z + bv.z;
    o.w = dw * inv * gv.w + bv.w;
    *reinterpret_cast<float4*>(&out[(size_t)point * 128 + 4 * lane]) = o;
  }
}

extern "C" void kernel_launch(void* const* d_in, const int* in_sizes, int n_in,
                              void* d_out, int out_size) {
  const float* pts = (const float*)d_in[0];
  const float* nbr = (const float*)d_in[1];
  const float* w1  = (const float*)d_in[2];
  const float* b1  = (const float*)d_in[3];
  const float* g1  = (const float*)d_in[4];
  const float* be1 = (const float*)d_in[5];
  const float* w2  = (const float*)d_in[6];
  const float* b2  = (const float*)d_in[7];
  const float* g2  = (const float*)d_in[8];
  const float* be2 = (const float*)d_in[9];
  const float* w3  = (const float*)d_in[10];
  const float* b3  = (const float*)d_in[11];
  const float* ow  = (const float*)d_in[12];
  const float* ob  = (const float*)d_in[13];
  const float* lg  = (const float*)d_in[14];
  const float* lb  = (const float*)d_in[15];

  const int P = in_sizes[1] / 96;          // B*N points
  const int grid = P / PTS;                // 4096

  cudaFuncSetAttribute(so3conv_kernel,
                       cudaFuncAttributeMaxDynamicSharedMemorySize,
                       (int)(SMEM_FLOATS * sizeof(float)));
  so3conv_kernel<<<grid, THREADS, SMEM_FLOATS * sizeof(float)>>>(
      pts, nbr, w1, b1, g1, be1, w2, b2, g2, be2, w3, b3,
      ow, ob, lg, lb, (float*)d_out);
}